// round 11
// baseline (speedup 1.0000x reference)
#include <cuda_runtime.h>
#include <math.h>

// ChannelAttention — R11: PERSISTENT fused kernel (grid = 148*6), last-CTA MLP
// tail per 4-blk group, inline in the persistent loop.
// x  : [B=8, O=8, S=32, C=64, 32, 32] fp32 (512 MB streamed once)
// w1 : [8,64,64], w2 : [8,64,64] fp32
// out: [B,O,S,C] fp32

#define C_DIM   64
#define HW_DIM  1024
#define O_DIM   8
#define S_DIM   32
#define NBLK    2048            // B*O*S
#define NGRP    512             // NBLK / 4
#define NBX     16384           // NBLK * 8 work tiles (8 rows each)
#define GRID    888             // 148 SMs * 6 CTAs
#define WPAD4   17              // padded weight row: 17 float4 (conflict-free)

__device__ float2       g_pool[NBLK * C_DIM];
__device__ unsigned int g_cnt[NGRP];      // zero-init; tail resets -> replay-safe

__global__ __launch_bounds__(256, 6)
void fused_kernel(const float* __restrict__ x,
                  const float* __restrict__ w1,
                  const float* __restrict__ w2,
                  float* __restrict__ out)
{
    __shared__ float4 ws4[C_DIM * WPAD4];      // staged w1, then reused for w2
    __shared__ __align__(16) float spm[4][C_DIM];
    __shared__ __align__(16) float spx[4][C_DIM];
    __shared__ __align__(16) float shs[4][C_DIM];
    __shared__ int sLast;

    const int tid  = threadIdx.x;
    const int lane = tid & 31;
    const int wid  = tid >> 5;                 // 8 warps

    for (int bx = blockIdx.x; bx < NBX; bx += GRID) {
        const int gw  = bx * 8 + wid;          // row id = blk*64 + c
        const int grp = bx >> 5;               // 32 bx-tiles per 4-blk group

        // ---------------- pooling: one warp per channel row ----------------
        const float4* row = reinterpret_cast<const float4*>(x)
                          + (size_t)gw * (HW_DIM / 4) + lane;

        float4 v0 = __ldcs(row + 0 * 32);
        float4 v1 = __ldcs(row + 1 * 32);
        float4 v2 = __ldcs(row + 2 * 32);
        float4 v3 = __ldcs(row + 3 * 32);
        float4 v4 = __ldcs(row + 4 * 32);
        float4 v5 = __ldcs(row + 5 * 32);
        float4 v6 = __ldcs(row + 6 * 32);
        float4 v7 = __ldcs(row + 7 * 32);

        float sa = (v0.x + v0.y) + (v0.z + v0.w);
        float sb = (v1.x + v1.y) + (v1.z + v1.w);
        float sc = (v2.x + v2.y) + (v2.z + v2.w);
        float sd = (v3.x + v3.y) + (v3.z + v3.w);
        sa += (v4.x + v4.y) + (v4.z + v4.w);
        sb += (v5.x + v5.y) + (v5.z + v5.w);
        sc += (v6.x + v6.y) + (v6.z + v6.w);
        sd += (v7.x + v7.y) + (v7.z + v7.w);

        float ma = fmaxf(fmaxf(v0.x, v0.y), fmaxf(v0.z, v0.w));
        float mb = fmaxf(fmaxf(v1.x, v1.y), fmaxf(v1.z, v1.w));
        float mc = fmaxf(fmaxf(v2.x, v2.y), fmaxf(v2.z, v2.w));
        float md = fmaxf(fmaxf(v3.x, v3.y), fmaxf(v3.z, v3.w));
        ma = fmaxf(ma, fmaxf(fmaxf(v4.x, v4.y), fmaxf(v4.z, v4.w)));
        mb = fmaxf(mb, fmaxf(fmaxf(v5.x, v5.y), fmaxf(v5.z, v5.w)));
        mc = fmaxf(mc, fmaxf(fmaxf(v6.x, v6.y), fmaxf(v6.z, v6.w)));
        md = fmaxf(md, fmaxf(fmaxf(v7.x, v7.y), fmaxf(v7.z, v7.w)));

        float s = (sa + sb) + (sc + sd);
        float m = fmaxf(fmaxf(ma, mb), fmaxf(mc, md));

        #pragma unroll
        for (int off = 16; off > 0; off >>= 1) {
            s += __shfl_xor_sync(0xFFFFFFFFu, s, off);
            m = fmaxf(m, __shfl_xor_sync(0xFFFFFFFFu, m, off));
        }
        if (lane == 0)
            g_pool[gw] = make_float2(s * (1.0f / (float)HW_DIM), m);
        __syncthreads();                        // all warps' pooled writes issued

        // ---------------- last-CTA election (per 4-blk group) ----------------
        if (tid == 0) {
            __threadfence();                    // release this tile's pooled writes
            unsigned int old = atomicAdd(&g_cnt[grp], 1u);
            if (old == 31u) { sLast = 1; g_cnt[grp] = 0u; }  // reset for replay
            else            { sLast = 0; }
        }
        __syncthreads();

        if (sLast) {
            // ------------ MLP tail: 4 blks, 256 threads fully active ----------
            const int o   = (grp >> 3) & 7;     // ((grp*4)/32)%8
            const int sub = tid >> 6;           // blk within group (0..3)
            const int n   = tid & 63;           // output/hidden index
            const int blk = grp * 4 + sub;

            {
                float2 p = __ldcg(&g_pool[blk * C_DIM + n]);  // bypass L1
                spm[sub][n] = p.x;
                spx[sub][n] = p.y;
            }

            // stage w1 (coalesced float4 -> padded rows)
            const float4* w1g4 = reinterpret_cast<const float4*>(w1 + (size_t)o * C_DIM * C_DIM);
            #pragma unroll
            for (int i = 0; i < 4; ++i) {
                int idx = tid + i * 256;        // 0..1023 float4s
                ws4[(idx >> 4) * WPAD4 + (idx & 15)] = __ldg(w1g4 + idx);
            }
            __syncthreads();

            // FC1 + relu
            {
                const float4* wr = ws4 + n * WPAD4;
                const float4* p4 = reinterpret_cast<const float4*>(spm[sub]);
                const float4* q4 = reinterpret_cast<const float4*>(spx[sub]);
                float am = 0.0f, ax = 0.0f;
                #pragma unroll
                for (int c4 = 0; c4 < 16; ++c4) {
                    float4 w = wr[c4];
                    float4 p = p4[c4];
                    float4 q = q4[c4];
                    am = fmaf(w.x, p.x, am); am = fmaf(w.y, p.y, am);
                    am = fmaf(w.z, p.z, am); am = fmaf(w.w, p.w, am);
                    ax = fmaf(w.x, q.x, ax); ax = fmaf(w.y, q.y, ax);
                    ax = fmaf(w.z, q.z, ax); ax = fmaf(w.w, q.w, ax);
                }
                shs[sub][n] = fmaxf(am, 0.0f) + fmaxf(ax, 0.0f);
            }
            __syncthreads();                    // FC1 done reading ws

            // stage w2 into the SAME buffer
            const float4* w2g4 = reinterpret_cast<const float4*>(w2 + (size_t)o * C_DIM * C_DIM);
            #pragma unroll
            for (int i = 0; i < 4; ++i) {
                int idx = tid + i * 256;
                ws4[(idx >> 4) * WPAD4 + (idx & 15)] = __ldg(w2g4 + idx);
            }
            __syncthreads();

            // FC2 + sigmoid (FC2 linear => single pass over summed hidden)
            {
                const float4* wr = ws4 + n * WPAD4;
                const float4* h4 = reinterpret_cast<const float4*>(shs[sub]);
                float a = 0.0f;
                #pragma unroll
                for (int c4 = 0; c4 < 16; ++c4) {
                    float4 w = wr[c4];
                    float4 h = h4[c4];
                    a = fmaf(w.x, h.x, a); a = fmaf(w.y, h.y, a);
                    a = fmaf(w.z, h.z, a); a = fmaf(w.w, h.w, a);
                }
                out[(size_t)blk * C_DIM + n] = 1.0f / (1.0f + __expf(-a));
            }
            __syncthreads();                    // ws/spm reuse safe for next iter
        }
    }
}

extern "C" void kernel_launch(void* const* d_in, const int* in_sizes, int n_in,
                              void* d_out, int out_size)
{
    const float* x  = (const float*)d_in[0];
    const float* w1 = (const float*)d_in[1];
    const float* w2 = (const float*)d_in[2];
    float* out = (float*)d_out;

    fused_kernel<<<GRID, 256>>>(x, w1, w2, out);
}

// round 12
// speedup vs baseline: 1.7099x; 1.7099x over previous
#include <cuda_runtime.h>
#include <math.h>

// ChannelAttention — R12: proven split. Pool untouched (73.5us, ~7TB/s, HBM
// wall). New MLP: one warp per blk, transposed smem weights, shfl broadcasts,
// single barrier, no inter-warp coupling.
// x  : [B=8, O=8, S=32, C=64, 32, 32] fp32 (512 MB)
// w1 : [8,64,64], w2 : [8,64,64] fp32
// out: [B,O,S,C] fp32

#define C_DIM   64
#define HW_DIM  1024
#define O_DIM   8
#define S_DIM   32
#define NBLK    2048            // B*O*S
#define FULLM   0xFFFFFFFFu

__device__ float2 g_pool[NBLK * C_DIM];

// ---------------- Kernel A: pooling (R4/R5 exact; at HBM roofline) ----------
__global__ __launch_bounds__(256, 6)
void pool_kernel(const float* __restrict__ x)
{
    const int lane = threadIdx.x & 31;
    const int gw   = blockIdx.x * 8 + (threadIdx.x >> 5);  // row = (blk, c)
    const float4* row = reinterpret_cast<const float4*>(x) + (size_t)gw * (HW_DIM / 4) + lane;

    float4 v0 = __ldcs(row + 0 * 32);
    float4 v1 = __ldcs(row + 1 * 32);
    float4 v2 = __ldcs(row + 2 * 32);
    float4 v3 = __ldcs(row + 3 * 32);
    float4 v4 = __ldcs(row + 4 * 32);
    float4 v5 = __ldcs(row + 5 * 32);
    float4 v6 = __ldcs(row + 6 * 32);
    float4 v7 = __ldcs(row + 7 * 32);

    float sa = (v0.x + v0.y) + (v0.z + v0.w);
    float sb = (v1.x + v1.y) + (v1.z + v1.w);
    float sc = (v2.x + v2.y) + (v2.z + v2.w);
    float sd = (v3.x + v3.y) + (v3.z + v3.w);
    sa += (v4.x + v4.y) + (v4.z + v4.w);
    sb += (v5.x + v5.y) + (v5.z + v5.w);
    sc += (v6.x + v6.y) + (v6.z + v6.w);
    sd += (v7.x + v7.y) + (v7.z + v7.w);

    float ma = fmaxf(fmaxf(v0.x, v0.y), fmaxf(v0.z, v0.w));
    float mb = fmaxf(fmaxf(v1.x, v1.y), fmaxf(v1.z, v1.w));
    float mc = fmaxf(fmaxf(v2.x, v2.y), fmaxf(v2.z, v2.w));
    float md = fmaxf(fmaxf(v3.x, v3.y), fmaxf(v3.z, v3.w));
    ma = fmaxf(ma, fmaxf(fmaxf(v4.x, v4.y), fmaxf(v4.z, v4.w)));
    mb = fmaxf(mb, fmaxf(fmaxf(v5.x, v5.y), fmaxf(v5.z, v5.w)));
    mc = fmaxf(mc, fmaxf(fmaxf(v6.x, v6.y), fmaxf(v6.z, v6.w)));
    md = fmaxf(md, fmaxf(fmaxf(v7.x, v7.y), fmaxf(v7.z, v7.w)));

    float s = (sa + sb) + (sc + sd);
    float m = fmaxf(fmaxf(ma, mb), fmaxf(mc, md));

    #pragma unroll
    for (int off = 16; off > 0; off >>= 1) {
        s += __shfl_xor_sync(FULLM, s, off);
        m = fmaxf(m, __shfl_xor_sync(FULLM, m, off));
    }
    if (lane == 0)
        g_pool[gw] = make_float2(s * (1.0f / (float)HW_DIM), m);
}

// ---------------- Kernel B: warp-per-blk MLP, transposed smem weights -------
// grid = 256 CTAs x 256 thr. CTA = 8 warps = 8 consecutive blks (same o).
// Stage w1,w2 transposed: t[c*65+n] = w[n*64+c]. One barrier. Then each warp
// independently: FC1 (shfl-broadcast pooled, stride-1 LDS), relu, FC2
// (shfl-broadcast hidden), sigmoid, coalesced store.
__global__ __launch_bounds__(256)
void mlp_kernel(const float* __restrict__ w1,
                const float* __restrict__ w2,
                float* __restrict__ out)
{
    __shared__ float t1[C_DIM * 65];
    __shared__ float t2[C_DIM * 65];

    const int tid  = threadIdx.x;
    const int lane = tid & 31;
    const int w    = tid >> 5;                 // warp = blk within CTA
    const int blk0 = blockIdx.x * 8;
    const int o    = (blk0 / S_DIM) % O_DIM;   // same for all 8 warps (8 | 32)

    // stage weights transposed (coalesced LDG; conflict-free STS: bank=(c+n)%32)
    const float* s1 = w1 + (size_t)o * C_DIM * C_DIM;
    const float* s2 = w2 + (size_t)o * C_DIM * C_DIM;
    #pragma unroll
    for (int i = 0; i < 16; ++i) {
        int idx = tid + i * 256;               // = n*64 + c
        int n = idx >> 6, c = idx & 63;
        t1[c * 65 + n] = __ldg(s1 + idx);
        t2[c * 65 + n] = __ldg(s2 + idx);
    }
    __syncthreads();

    const int blk = blk0 + w;
    float2 pa = g_pool[blk * C_DIM + lane];        // coalesced
    float2 pb = g_pool[blk * C_DIM + 32 + lane];
    const float pml = pa.x, pxl = pa.y;            // pooled mean/max, c=lane
    const float pmh = pb.x, pxh = pb.y;            // c = lane+32

    // FC1: lane computes hidden n0=lane and n1=lane+32
    float am0 = 0.f, ax0 = 0.f, am1 = 0.f, ax1 = 0.f;
    #pragma unroll 8
    for (int c = 0; c < 32; ++c) {
        float pmc = __shfl_sync(FULLM, pml, c);
        float pxc = __shfl_sync(FULLM, pxl, c);
        float wl  = t1[c * 65 + lane];
        float wh  = t1[c * 65 + 32 + lane];
        am0 = fmaf(pmc, wl, am0); ax0 = fmaf(pxc, wl, ax0);
        am1 = fmaf(pmc, wh, am1); ax1 = fmaf(pxc, wh, ax1);
    }
    #pragma unroll 8
    for (int c = 32; c < 64; ++c) {
        float pmc = __shfl_sync(FULLM, pmh, c - 32);
        float pxc = __shfl_sync(FULLM, pxh, c - 32);
        float wl  = t1[c * 65 + lane];
        float wh  = t1[c * 65 + 32 + lane];
        am0 = fmaf(pmc, wl, am0); ax0 = fmaf(pxc, wl, ax0);
        am1 = fmaf(pmc, wh, am1); ax1 = fmaf(pxc, wh, ax1);
    }
    const float hl = fmaxf(am0, 0.f) + fmaxf(ax0, 0.f);   // h[lane]
    const float hh = fmaxf(am1, 0.f) + fmaxf(ax1, 0.f);   // h[lane+32]

    // FC2: broadcast hidden via shfl, weights stride-1 from t2
    float a0 = 0.f, a1 = 0.f;
    #pragma unroll 8
    for (int h = 0; h < 32; ++h) {
        float hc = __shfl_sync(FULLM, hl, h);
        float wl = t2[h * 65 + lane];
        float wh = t2[h * 65 + 32 + lane];
        a0 = fmaf(hc, wl, a0); a1 = fmaf(hc, wh, a1);
    }
    #pragma unroll 8
    for (int h = 32; h < 64; ++h) {
        float hc = __shfl_sync(FULLM, hh, h - 32);
        float wl = t2[h * 65 + lane];
        float wh = t2[h * 65 + 32 + lane];
        a0 = fmaf(hc, wl, a0); a1 = fmaf(hc, wh, a1);
    }

    out[(size_t)blk * C_DIM + lane]      = 1.0f / (1.0f + __expf(-a0));
    out[(size_t)blk * C_DIM + 32 + lane] = 1.0f / (1.0f + __expf(-a1));
}

extern "C" void kernel_launch(void* const* d_in, const int* in_sizes, int n_in,
                              void* d_out, int out_size)
{
    const float* x  = (const float*)d_in[0];
    const float* w1 = (const float*)d_in[1];
    const float* w2 = (const float*)d_in[2];
    float* out = (float*)d_out;

    pool_kernel<<<NBLK * 8, 256>>>(x);
    mlp_kernel<<<NBLK / 8, 256>>>(w1, w2, out);
}